// round 13
// baseline (speedup 1.0000x reference)
#include <cuda_runtime.h>
#include <cuda_fp16.h>
#include <cstdint>
#include <math.h>

#define BSZ 1024
#define DIM 128
#define K2  256     // concatenated feature length

// ---------------- helpers --------------------------------------------------
__device__ __forceinline__ uint32_t smem_u32(const void* p) {
    uint32_t a;
    asm("{ .reg .u64 t; cvta.to.shared.u64 t, %1; cvt.u32.u64 %0, t; }"
        : "=r"(a) : "l"(p));
    return a;
}
#define LDSM4(r0, r1, r2, r3, addr) \
    asm volatile("ldmatrix.sync.aligned.m8n8.x4.shared.b16 {%0,%1,%2,%3}, [%4];" \
                 : "=r"(r0), "=r"(r1), "=r"(r2), "=r"(r3) : "r"(addr))

__device__ __forceinline__ void mma_f16(float c[4],
                                        uint32_t a0, uint32_t a1, uint32_t a2, uint32_t a3,
                                        uint32_t b0, uint32_t b1) {
    asm volatile(
        "mma.sync.aligned.m16n8k16.row.col.f32.f16.f16.f32 "
        "{%0,%1,%2,%3}, {%4,%5,%6,%7}, {%8,%9}, {%0,%1,%2,%3};"
        : "+f"(c[0]), "+f"(c[1]), "+f"(c[2]), "+f"(c[3])
        : "r"(a0), "r"(a1), "r"(a2), "r"(a3), "r"(b0), "r"(b1));
}

// ---------------------------------------------------------------------------
// Single fused kernel, zero global scratch.
// 136 upper-triangular 64x64 tiles, 1 CTA/SM, 512 threads (16 warps, 4m x 4n,
// warp tile 16x16).
// Phase 1 (prologue): each CTA loads x/dc rows [i0,i0+64) u [j0,j0+64) and
//   computes Z = [s1*x | s2*exp(1-dc)] fp16 directly into smem (pitch 528 B,
//   528 % 128 == 16 -> LDSM conflict-free), plus row norms into s_c.
//   Diagonal CTAs (bi==bj) prep only 64 rows; B aliases A.
// Phase 2: 16 k-step fp16 mma mainloop (A frags XOR-negated for k<128,
//   register double-buffered).
// Phase 3: epilogue out[i][j] = (i==j) ? 1 : DIM/(c_i+c_j+S); off-diagonal
//   tiles also store the transposed block via an smem bounce (region T).
//   smem: A @0 (33792) | B @33792 | T @67584 (64*65*4) ; 84224 B dynamic.
// ---------------------------------------------------------------------------
#define ROWB   528
#define OFF_B  33792
#define OFF_T  67584
#define SMEM_BYTES 84224
#define TP 65   // transpose bounce pitch (floats)

__global__ void __launch_bounds__(512, 1)
fused_kernel(const float* __restrict__ x, const float* __restrict__ dc,
             const float* __restrict__ ap, float* __restrict__ out) {
    extern __shared__ __align__(16) char smem[];
    __shared__ float s_c[128];

    const int tid = threadIdx.x;
    const int wid = tid >> 5;
    const int lid = tid & 31;
    const int wm  = wid >> 2;          // 0..3 -> m offset wm*16
    const int wn  = wid & 3;           // 0..3 -> n offset wn*16

    // ---- decode upper-triangular tile (bi <= bj) ----
    int bi = 0, rem = blockIdx.x;
    while (rem >= 16 - bi) { rem -= 16 - bi; bi++; }
    const int bj = bi + rem;
    const int i0 = bi * 64;
    const int j0 = bj * 64;
    const bool diag = (bi == bj);

    const uint32_t sb = smem_u32(smem);

    // ---- phase 1: in-CTA prep of A (and B) tiles + row norms ----
    {
        const float a  = ap[0];
        const float s1 = sqrtf(2.0f * (1.0f - a));
        const float s2 = sqrtf(a);
        const int nrows = diag ? 64 : 128;
        const int d = lid * 4;

        for (int lr = wid; lr < nrows; lr += 16) {
            const int grow = (lr < 64) ? (i0 + lr) : (j0 + lr - 64);
            const float4 xv = *(const float4*)&x[grow * DIM + d];
            const float4 dv = *(const float4*)&dc[grow * DIM + d];

            __half zb[4] = { __float2half_rn(s1 * xv.x), __float2half_rn(s1 * xv.y),
                             __float2half_rn(s1 * xv.z), __float2half_rn(s1 * xv.w) };
            __half hb[4] = { __float2half_rn(s2 * __expf(1.0f - dv.x)),
                             __float2half_rn(s2 * __expf(1.0f - dv.y)),
                             __float2half_rn(s2 * __expf(1.0f - dv.z)),
                             __float2half_rn(s2 * __expf(1.0f - dv.w)) };

            char* rowp = smem + lr * ROWB;
            *(uint2*)(rowp + d * 2)       = *(uint2*)zb;
            *(uint2*)(rowp + 256 + d * 2) = *(uint2*)hb;

            float s = xv.x * xv.x + xv.y * xv.y + xv.z * xv.z + xv.w * xv.w;
#pragma unroll
            for (int o = 16; o; o >>= 1) s += __shfl_down_sync(0xffffffffu, s, o);
            if (lid == 0) s_c[lr] = (1.0f - a) * s;
        }
    }
    __syncthreads();

    // ---- phase 2: mainloop ----
    const uint32_t arow = lid & 15;
    const uint32_t acol = (lid >> 4) * 16;            // bytes
    const uint32_t brow = (lid & 7) | (((lid >> 4) & 1) << 3);
    const uint32_t bcol = ((lid >> 3) & 1) * 16;
    const uint32_t boff = diag ? 0u : (uint32_t)OFF_B;
    const uint32_t aAd = sb + (wm * 16 + arow) * ROWB + acol;
    const uint32_t bAd = sb + boff + (wn * 16 + brow) * ROWB + bcol;

    float acc[2][4] = {};
    uint32_t F[2][8];   // [set][ a0..3 | b0..3 ]

    auto ldf = [&](uint32_t* f, int ks) {
        const uint32_t ko = (uint32_t)ks * 32;
        LDSM4(f[0], f[1], f[2], f[3], aAd + ko);
        LDSM4(f[4], f[5], f[6], f[7], bAd + ko);
        if (ks < 8) {   // W's first K-half is -Z: negate A frags (packed fp16)
#pragma unroll
            for (int q = 0; q < 4; q++) f[q] ^= 0x80008000u;
        }
    };
    auto domma = [&](uint32_t* f) {
        mma_f16(acc[0], f[0], f[1], f[2], f[3], f[4], f[5]);
        mma_f16(acc[1], f[0], f[1], f[2], f[3], f[6], f[7]);
    };

    ldf(F[0], 0);
#pragma unroll
    for (int ks = 0; ks < 15; ks++) {
        ldf(F[(ks + 1) & 1], ks + 1);
        domma(F[ks & 1]);
    }
    domma(F[1]);

    // ---- phase 3: epilogue ----
    const int g = lid >> 2;
    const int t = lid & 3;
    const int lia = wm * 16 + g;        // local A row
    const int lib = lia + 8;
    const int ia = i0 + lia;
    const int ib = i0 + lib;
    const int jb = diag ? 0 : 64;       // s_c index base for B rows
    const float cia = s_c[lia];
    const float cib = s_c[lib];

    float res[2][4];
#pragma unroll
    for (int nf = 0; nf < 2; nf++) {
        const int lj = wn * 16 + nf * 8 + t * 2;
        const int j  = j0 + lj;
        const float cj0 = s_c[jb + lj];
        const float cj1 = s_c[jb + lj + 1];
        const float* s = acc[nf];
        res[nf][0] = (ia == j)     ? 1.0f : __fdividef((float)DIM, cia + cj0 + s[0]);
        res[nf][1] = (ia == j + 1) ? 1.0f : __fdividef((float)DIM, cia + cj1 + s[1]);
        res[nf][2] = (ib == j)     ? 1.0f : __fdividef((float)DIM, cib + cj0 + s[2]);
        res[nf][3] = (ib == j + 1) ? 1.0f : __fdividef((float)DIM, cib + cj1 + s[3]);

        *(float2*)&out[ia * BSZ + j] = make_float2(res[nf][0], res[nf][1]);
        *(float2*)&out[ib * BSZ + j] = make_float2(res[nf][2], res[nf][3]);
    }

    // ---- transposed block for off-diagonal tiles (own smem region T) ----
    if (!diag) {
        float* T = (float*)(smem + OFF_T);
#pragma unroll
        for (int nf = 0; nf < 2; nf++) {
            const int lj = wn * 16 + nf * 8 + t * 2;
            T[lia * TP + lj]     = res[nf][0];
            T[lia * TP + lj + 1] = res[nf][1];
            T[lib * TP + lj]     = res[nf][2];
            T[lib * TP + lj + 1] = res[nf][3];
        }
        __syncthreads();
        // coalesced store of the transpose: out[j0+r][i0+c] = T[c][r]
#pragma unroll
        for (int idx = tid; idx < 1024; idx += 512) {
            const int r  = idx >> 4;
            const int c4 = (idx & 15) * 4;
            float4 v;
            v.x = T[(c4 + 0) * TP + r];
            v.y = T[(c4 + 1) * TP + r];
            v.z = T[(c4 + 2) * TP + r];
            v.w = T[(c4 + 3) * TP + r];
            *(float4*)&out[(j0 + r) * BSZ + i0 + c4] = v;
        }
    }
}

// ---------------------------------------------------------------------------
extern "C" void kernel_launch(void* const* d_in, const int* in_sizes, int n_in,
                              void* d_out, int out_size) {
    const float* x  = (const float*)d_in[0];
    const float* dc = (const float*)d_in[1];
    const float* ap = (const float*)d_in[2];
    float* out = (float*)d_out;

    cudaFuncSetAttribute(fused_kernel, cudaFuncAttributeMaxDynamicSharedMemorySize, SMEM_BYTES);
    fused_kernel<<<136, 512, SMEM_BYTES>>>(x, dc, ap, out);
}

// round 14
// speedup vs baseline: 1.0338x; 1.0338x over previous
#include <cuda_runtime.h>
#include <cuda_fp16.h>
#include <cstdint>
#include <math.h>

#define BSZ 1024
#define DIM 128
#define K2  256     // concatenated feature length

// ---------------- helpers --------------------------------------------------
__device__ __forceinline__ uint32_t smem_u32(const void* p) {
    uint32_t a;
    asm("{ .reg .u64 t; cvta.to.shared.u64 t, %1; cvt.u32.u64 %0, t; }"
        : "=r"(a) : "l"(p));
    return a;
}
#define LDSM4(r0, r1, r2, r3, addr) \
    asm volatile("ldmatrix.sync.aligned.m8n8.x4.shared.b16 {%0,%1,%2,%3}, [%4];" \
                 : "=r"(r0), "=r"(r1), "=r"(r2), "=r"(r3) : "r"(addr))
#define MBARRIER_INIT(addr, cnt) \
    asm volatile("mbarrier.init.shared.b64 [%0], %1;" :: "r"(addr), "r"(cnt) : "memory")
#define MBARRIER_EXPECT_TX(addr, bytes) \
    asm volatile("mbarrier.arrive.expect_tx.shared.b64 _, [%0], %1;" \
                 :: "r"(addr), "r"((uint32_t)(bytes)) : "memory")
#define BULK_G2S(dst, src, bytes, mbar) \
    asm volatile("cp.async.bulk.shared::cta.global.mbarrier::complete_tx::bytes " \
                 "[%0], [%1], %2, [%3];" \
                 :: "r"(dst), "l"(src), "r"((uint32_t)(bytes)), "r"(mbar) : "memory")
#define MBARRIER_WAIT_PARITY(addr, par) do {                                      \
    uint32_t _m = (addr), _p = (par), _d;                                         \
    asm volatile("{\n\t.reg .pred p;\n\t"                                         \
        "mbarrier.try_wait.parity.acquire.cta.shared::cta.b64 p, [%1], %2;\n\t"   \
        "selp.b32 %0, 1, 0, p;\n\t}" : "=r"(_d) : "r"(_m), "r"(_p) : "memory");   \
    if (!_d) {                                                                    \
        asm volatile("{\n\t.reg .pred P1;\n\t"                                    \
            "WL_%=:\n\t"                                                          \
            "mbarrier.try_wait.parity.acquire.cta.shared::cta.b64 P1, [%0], %1, 0x989680;\n\t" \
            "@P1 bra.uni WD_%=;\n\tbra.uni WL_%=;\n\tWD_%=:\n\t}"                 \
            :: "r"(_m), "r"(_p) : "memory");                                      \
    }                                                                             \
} while (0)

__device__ __forceinline__ void mma_f16(float c[4],
                                        uint32_t a0, uint32_t a1, uint32_t a2, uint32_t a3,
                                        uint32_t b0, uint32_t b1) {
    asm volatile(
        "mma.sync.aligned.m16n8k16.row.col.f32.f16.f16.f32 "
        "{%0,%1,%2,%3}, {%4,%5,%6,%7}, {%8,%9}, {%0,%1,%2,%3};"
        : "+f"(c[0]), "+f"(c[1]), "+f"(c[2]), "+f"(c[3])
        : "r"(a0), "r"(a1), "r"(a2), "r"(a3), "r"(b0), "r"(b1));
}

// ---------------------------------------------------------------------------
// Single fused kernel, zero global scratch, bulk-DMA staged inputs.
// 136 upper-triangular 64x64 tiles, 1 CTA/SM, 512 threads (16 warps, 4m x 4n,
// warp tile 16x16).
// Phase 1: bulk-DMA x/dc row slices into smem staging S (4 x 32KB; two
//   mbarriers so A-side conversion overlaps B-side arrival), then convert
//   from smem: Z = [s1*x | s2*exp(1-dc)] fp16 into A/B (pitch 528 ->
//   conflict-free LDSM) + row norms in s_c.  Diagonal CTAs: A only, B=A.
// Phase 2: 16 k-step fp16 mma mainloop (A frags XOR-negated for k<128).
// Phase 3: epilogue + transposed block via smem bounce T (aliases S).
//   smem: A @0 | B @33792 | S @67584 (131072) ; T @67584 ; 198656 B dynamic.
// ---------------------------------------------------------------------------
#define ROWB   528
#define OFF_B  33792
#define OFF_S  67584
#define SMEM_BYTES 198656
#define TP 65   // transpose bounce pitch (floats)

__global__ void __launch_bounds__(512, 1)
fused_kernel(const float* __restrict__ x, const float* __restrict__ dc,
             const float* __restrict__ ap, float* __restrict__ out) {
    extern __shared__ __align__(16) char smem[];
    __shared__ __align__(8) uint64_t s_mbar[2];
    __shared__ float s_c[128];

    const int tid = threadIdx.x;
    const int wid = tid >> 5;
    const int lid = tid & 31;
    const int wm  = wid >> 2;          // 0..3 -> m offset wm*16
    const int wn  = wid & 3;           // 0..3 -> n offset wn*16

    // ---- decode upper-triangular tile (bi <= bj) ----
    int bi = 0, rem = blockIdx.x;
    while (rem >= 16 - bi) { rem -= 16 - bi; bi++; }
    const int bj = bi + rem;
    const int i0 = bi * 64;
    const int j0 = bj * 64;
    const bool diag = (bi == bj);

    const uint32_t sb = smem_u32(smem);
    const uint32_t mb = smem_u32(s_mbar);

    // ---- phase 1a: stage raw inputs via bulk DMA ----
    if (tid == 0) {
        MBARRIER_INIT(mb, 1);
        MBARRIER_INIT(mb + 8, 1);
    }
    __syncthreads();
    if (tid == 0) {
        MBARRIER_EXPECT_TX(mb, 65536);
        BULK_G2S(sb + OFF_S,         x  + (size_t)i0 * DIM, 32768, mb);
        BULK_G2S(sb + OFF_S + 32768, dc + (size_t)i0 * DIM, 32768, mb);
        if (!diag) {
            MBARRIER_EXPECT_TX(mb + 8, 65536);
            BULK_G2S(sb + OFF_S + 65536, x  + (size_t)j0 * DIM, 32768, mb + 8);
            BULK_G2S(sb + OFF_S + 98304, dc + (size_t)j0 * DIM, 32768, mb + 8);
        }
    }

    // ---- phase 1b: convert from smem staging into A/B fp16 tiles ----
    {
        const float a  = ap[0];
        const float s1 = sqrtf(2.0f * (1.0f - a));
        const float s2 = sqrtf(a);
        const int side = wid >> 3;          // warps 0-7: A rows; 8-15: B rows
        if (!diag || side == 0) {
            MBARRIER_WAIT_PARITY(mb + 8 * side, 0);
            const char* S = smem + OFF_S + side * 65536;
            char* Dst = smem + side * OFF_B;
#pragma unroll
            for (int r = 0; r < 8; r++) {
                const int lr = (wid & 7) * 8 + r;    // row within side, 0..63
                const float4 xv = *(const float4*)(S + lr * 512 + lid * 16);
                const float4 dv = *(const float4*)(S + 32768 + lr * 512 + lid * 16);

                __half zb[4] = { __float2half_rn(s1 * xv.x), __float2half_rn(s1 * xv.y),
                                 __float2half_rn(s1 * xv.z), __float2half_rn(s1 * xv.w) };
                __half hb[4] = { __float2half_rn(s2 * __expf(1.0f - dv.x)),
                                 __float2half_rn(s2 * __expf(1.0f - dv.y)),
                                 __float2half_rn(s2 * __expf(1.0f - dv.z)),
                                 __float2half_rn(s2 * __expf(1.0f - dv.w)) };

                char* rowp = Dst + lr * ROWB;
                *(uint2*)(rowp + lid * 8)       = *(uint2*)zb;
                *(uint2*)(rowp + 256 + lid * 8) = *(uint2*)hb;

                float s = xv.x * xv.x + xv.y * xv.y + xv.z * xv.z + xv.w * xv.w;
#pragma unroll
                for (int o = 16; o; o >>= 1) s += __shfl_down_sync(0xffffffffu, s, o);
                if (lid == 0) s_c[side * 64 + lr] = (1.0f - a) * s;
            }
        }
    }
    __syncthreads();

    // ---- phase 2: mainloop ----
    const uint32_t arow = lid & 15;
    const uint32_t acol = (lid >> 4) * 16;            // bytes
    const uint32_t brow = (lid & 7) | (((lid >> 4) & 1) << 3);
    const uint32_t bcol = ((lid >> 3) & 1) * 16;
    const uint32_t boff = diag ? 0u : (uint32_t)OFF_B;
    const uint32_t aAd = sb + (wm * 16 + arow) * ROWB + acol;
    const uint32_t bAd = sb + boff + (wn * 16 + brow) * ROWB + bcol;

    float acc[2][4] = {};
    uint32_t F[2][8];   // [set][ a0..3 | b0..3 ]

    auto ldf = [&](uint32_t* f, int ks) {
        const uint32_t ko = (uint32_t)ks * 32;
        LDSM4(f[0], f[1], f[2], f[3], aAd + ko);
        LDSM4(f[4], f[5], f[6], f[7], bAd + ko);
        if (ks < 8) {   // W's first K-half is -Z: negate A frags (packed fp16)
#pragma unroll
            for (int q = 0; q < 4; q++) f[q] ^= 0x80008000u;
        }
    };
    auto domma = [&](uint32_t* f) {
        mma_f16(acc[0], f[0], f[1], f[2], f[3], f[4], f[5]);
        mma_f16(acc[1], f[0], f[1], f[2], f[3], f[6], f[7]);
    };

    ldf(F[0], 0);
#pragma unroll
    for (int ks = 0; ks < 15; ks++) {
        ldf(F[(ks + 1) & 1], ks + 1);
        domma(F[ks & 1]);
    }
    domma(F[1]);

    // ---- phase 3: epilogue ----
    const int g = lid >> 2;
    const int t = lid & 3;
    const int lia = wm * 16 + g;        // local A row
    const int lib = lia + 8;
    const int ia = i0 + lia;
    const int ib = i0 + lib;
    const int jb = diag ? 0 : 64;       // s_c index base for B rows
    const float cia = s_c[lia];
    const float cib = s_c[lib];

    float res[2][4];
#pragma unroll
    for (int nf = 0; nf < 2; nf++) {
        const int lj = wn * 16 + nf * 8 + t * 2;
        const int j  = j0 + lj;
        const float cj0 = s_c[jb + lj];
        const float cj1 = s_c[jb + lj + 1];
        const float* s = acc[nf];
        res[nf][0] = (ia == j)     ? 1.0f : __fdividef((float)DIM, cia + cj0 + s[0]);
        res[nf][1] = (ia == j + 1) ? 1.0f : __fdividef((float)DIM, cia + cj1 + s[1]);
        res[nf][2] = (ib == j)     ? 1.0f : __fdividef((float)DIM, cib + cj0 + s[2]);
        res[nf][3] = (ib == j + 1) ? 1.0f : __fdividef((float)DIM, cib + cj1 + s[3]);

        *(float2*)&out[ia * BSZ + j] = make_float2(res[nf][0], res[nf][1]);
        *(float2*)&out[ib * BSZ + j] = make_float2(res[nf][2], res[nf][3]);
    }

    // ---- transposed block for off-diagonal tiles (T aliases staging S) ----
    if (!diag) {
        float* T = (float*)(smem + OFF_S);
#pragma unroll
        for (int nf = 0; nf < 2; nf++) {
            const int lj = wn * 16 + nf * 8 + t * 2;
            T[lia * TP + lj]     = res[nf][0];
            T[lia * TP + lj + 1] = res[nf][1];
            T[lib * TP + lj]     = res[nf][2];
            T[lib * TP + lj + 1] = res[nf][3];
        }
        __syncthreads();
        // coalesced store of the transpose: out[j0+r][i0+c] = T[c][r]
#pragma unroll
        for (int idx = tid; idx < 1024; idx += 512) {
            const int r  = idx >> 4;
            const int c4 = (idx & 15) * 4;
            float4 v;
            v.x = T[(c4 + 0) * TP + r];
            v.y = T[(c4 + 1) * TP + r];
            v.z = T[(c4 + 2) * TP + r];
            v.w = T[(c4 + 3) * TP + r];
            *(float4*)&out[(j0 + r) * BSZ + i0 + c4] = v;
        }
    }
}

// ---------------------------------------------------------------------------
extern "C" void kernel_launch(void* const* d_in, const int* in_sizes, int n_in,
                              void* d_out, int out_size) {
    const float* x  = (const float*)d_in[0];
    const float* dc = (const float*)d_in[1];
    const float* ap = (const float*)d_in[2];
    float* out = (float*)d_out;

    cudaFuncSetAttribute(fused_kernel, cudaFuncAttributeMaxDynamicSharedMemorySize, SMEM_BYTES);
    fused_kernel<<<136, 512, SMEM_BYTES>>>(x, dc, ap, out);
}